// round 1
// baseline (speedup 1.0000x reference)
#include <cuda_runtime.h>
#include <math.h>

#define B_  128
#define T_  1024
#define NX_ 256
#define NH_ 512
#define NY_ 256

// Persistent state for the sequential kernel (allocation-free scratch).
__device__ float g_h[2][B_ * NH_];
__device__ unsigned g_bar_count = 0;
__device__ unsigned g_bar_gen = 0;

// ---------------------------------------------------------------------------
// Generic NT SGEMM: C[m][n] = sum_k A[m][k] * B[n][k]
// A: [M][K] row-major, Bm: [N][K] row-major, C: [M][N] row-major.
// ---------------------------------------------------------------------------
template <int BM, int BN, int BK, int TM, int TN, int NT>
__global__ __launch_bounds__(NT) void sgemm_nt(
    const float* __restrict__ A,
    const float* __restrict__ Bm,
    float* __restrict__ C,
    int M, int N, int K)
{
    __shared__ float As[BK][BM];
    __shared__ float Bs[BK][BN];

    const int tid = threadIdx.x;
    const int m0 = blockIdx.y * BM;
    const int n0 = blockIdx.x * BN;
    const int tx = tid % (BN / TN);   // column group
    const int ty = tid / (BN / TN);   // row group

    float acc[TM][TN];
#pragma unroll
    for (int i = 0; i < TM; i++)
#pragma unroll
        for (int j = 0; j < TN; j++) acc[i][j] = 0.0f;

    for (int k0 = 0; k0 < K; k0 += BK) {
        // Load A tile (BM x BK) transposed into As[k][m]
#pragma unroll
        for (int i = tid; i < BM * (BK / 4); i += NT) {
            int m = i / (BK / 4);
            int kq = (i % (BK / 4)) * 4;
            float4 v = *(const float4*)(A + (long)(m0 + m) * K + k0 + kq);
            As[kq + 0][m] = v.x;
            As[kq + 1][m] = v.y;
            As[kq + 2][m] = v.z;
            As[kq + 3][m] = v.w;
        }
        // Load B tile (BN x BK) transposed into Bs[k][n]
#pragma unroll
        for (int i = tid; i < BN * (BK / 4); i += NT) {
            int n = i / (BK / 4);
            int kq = (i % (BK / 4)) * 4;
            float4 v = *(const float4*)(Bm + (long)(n0 + n) * K + k0 + kq);
            Bs[kq + 0][n] = v.x;
            Bs[kq + 1][n] = v.y;
            Bs[kq + 2][n] = v.z;
            Bs[kq + 3][n] = v.w;
        }
        __syncthreads();

#pragma unroll
        for (int k = 0; k < BK; ++k) {
            float a[TM], b[TN];
#pragma unroll
            for (int i = 0; i < TM; i++) a[i] = As[k][ty * TM + i];
#pragma unroll
            for (int j = 0; j < TN; j++) b[j] = Bs[k][tx * TN + j];
#pragma unroll
            for (int i = 0; i < TM; i++)
#pragma unroll
                for (int j = 0; j < TN; j++) acc[i][j] = fmaf(a[i], b[j], acc[i][j]);
        }
        __syncthreads();
    }

    // Write back (TN == 4 assumed: vectorized)
#pragma unroll
    for (int i = 0; i < TM; i++) {
        float4 v = make_float4(acc[i][0], acc[i][1], acc[i][2], acc[i][3]);
        *(float4*)(C + (long)(m0 + ty * TM + i) * N + n0 + tx * TN) = v;
    }
}

// ---------------------------------------------------------------------------
// Persistent sequential RNN kernel.
// Grid = 128 CTAs (8 b-tiles x 16 j-tiles), 256 threads each.
// Per step: h_new[b][j] = tanh(pre[b][t][j] + sum_k h_prev[b][k] * Wh[j][k])
// pre lives in the hs output region and is overwritten in place by h.
// Wh tile (32 rows x 512) stays resident in SMEM for all 1024 steps.
// 8 warps split K (64 each); 4x4 register tiles; SMEM tree-reduce; grid barrier.
// ---------------------------------------------------------------------------
#define SEQ_NBLK 128

__device__ __forceinline__ void grid_sync_all()
{
    __threadfence();
    __syncthreads();
    if (threadIdx.x == 0) {
        volatile unsigned* genp = &g_bar_gen;
        unsigned gen = *genp;
        unsigned t = atomicAdd(&g_bar_count, 1u);
        if (t == SEQ_NBLK - 1) {
            g_bar_count = 0;
            __threadfence();
            atomicExch(&g_bar_gen, gen + 1);
        } else {
            while (*genp == gen) { }
        }
    }
    __syncthreads();
}

__global__ __launch_bounds__(256, 1) void rnn_seq(
    const float* __restrict__ Wh,   // [NH][NH]
    float* __restrict__ hs)         // [B][T][NH]: pre in, h out (in place)
{
    extern __shared__ float sm[];
    float* whT = sm;                        // [512][32]  Wh tile, transposed (k-major)
    float* hT  = sm + 512 * 32;             // [512][16]  h tile, transposed
    float* red = sm + 512 * 32 + 512 * 16;  // [8][512]   per-warp partials

    const int tid  = threadIdx.x;
    const int wid  = tid >> 5;
    const int lane = tid & 31;

    const int jt = blockIdx.x & 15;   // 16 j-tiles of 32
    const int bt = blockIdx.x >> 4;   // 8  b-tiles of 16
    const int j0g = jt * 32;
    const int b0g = bt * 16;

    // Load resident Wh tile (32 x 512) transposed: whT[k][j]
    for (int i = tid; i < 32 * 128; i += 256) {
        int j  = i >> 7;
        int kq = (i & 127) * 4;
        float4 v = *(const float4*)(Wh + (long)(j0g + j) * NH_ + kq);
        whT[(kq + 0) * 32 + j] = v.x;
        whT[(kq + 1) * 32 + j] = v.y;
        whT[(kq + 2) * 32 + j] = v.z;
        whT[(kq + 3) * 32 + j] = v.w;
    }

    const int bg = lane >> 3;       // 0..3 -> b offset bg*4
    const int jg = lane & 7;        // 0..7 -> j offset jg*4
    const int kw0 = wid * 64;       // this warp's K chunk

    __syncthreads();

    for (int t = 0; t < T_; ++t) {
        const float* hin = g_h[t & 1];
        float* hout      = g_h[(t + 1) & 1];

        // Load h tile (16 x 512) transposed into hT[k][b], L1-bypassed.
        for (int i = tid; i < 16 * 128; i += 256) {
            int b  = i >> 7;
            int kq = (i & 127) * 4;
            float4 v = __ldcg((const float4*)(hin + (long)(b0g + b) * NH_ + kq));
            hT[(kq + 0) * 16 + b] = v.x;
            hT[(kq + 1) * 16 + b] = v.y;
            hT[(kq + 2) * 16 + b] = v.z;
            hT[(kq + 3) * 16 + b] = v.w;
        }
        __syncthreads();

        float acc[4][4];
#pragma unroll
        for (int i = 0; i < 4; i++)
#pragma unroll
            for (int j = 0; j < 4; j++) acc[i][j] = 0.0f;

#pragma unroll 4
        for (int k = kw0; k < kw0 + 64; ++k) {
            float4 a = *(const float4*)(hT  + k * 16 + bg * 4);
            float4 w = *(const float4*)(whT + k * 32 + jg * 4);
            acc[0][0] = fmaf(a.x, w.x, acc[0][0]);
            acc[0][1] = fmaf(a.x, w.y, acc[0][1]);
            acc[0][2] = fmaf(a.x, w.z, acc[0][2]);
            acc[0][3] = fmaf(a.x, w.w, acc[0][3]);
            acc[1][0] = fmaf(a.y, w.x, acc[1][0]);
            acc[1][1] = fmaf(a.y, w.y, acc[1][1]);
            acc[1][2] = fmaf(a.y, w.z, acc[1][2]);
            acc[1][3] = fmaf(a.y, w.w, acc[1][3]);
            acc[2][0] = fmaf(a.z, w.x, acc[2][0]);
            acc[2][1] = fmaf(a.z, w.y, acc[2][1]);
            acc[2][2] = fmaf(a.z, w.z, acc[2][2]);
            acc[2][3] = fmaf(a.z, w.w, acc[2][3]);
            acc[3][0] = fmaf(a.w, w.x, acc[3][0]);
            acc[3][1] = fmaf(a.w, w.y, acc[3][1]);
            acc[3][2] = fmaf(a.w, w.z, acc[3][2]);
            acc[3][3] = fmaf(a.w, w.w, acc[3][3]);
        }

        // Stash this warp's partials
#pragma unroll
        for (int i = 0; i < 4; i++)
#pragma unroll
            for (int j = 0; j < 4; j++)
                red[wid * 512 + (bg * 4 + i) * 32 + (jg * 4 + j)] = acc[i][j];
        __syncthreads();

        // Reduce across 8 warps, add pre, tanh, write h + hs.
        for (int oo = tid; oo < 512; oo += 256) {
            int b = oo >> 5;
            int j = oo & 31;
            long hs_idx = ((long)(b0g + b) * T_ + t) * NH_ + (j0g + j);
            float s = hs[hs_idx];  // pre-activation from the i2h GEMM
#pragma unroll
            for (int w = 0; w < 8; w++) s += red[w * 512 + oo];
            float hv = tanhf(s);
            hs[hs_idx] = hv;
            hout[(long)(b0g + b) * NH_ + (j0g + j)] = hv;
        }

        grid_sync_all();
    }
}

// ---------------------------------------------------------------------------
// Launch
// ---------------------------------------------------------------------------
extern "C" void kernel_launch(void* const* d_in, const int* in_sizes, int n_in,
                              void* d_out, int out_size)
{
    const float* x  = (const float*)d_in[0];  // [B][T][NX]
    const float* h0 = (const float*)d_in[1];  // [B][NH]
    const float* Wi = (const float*)d_in[2];  // [NH][NX]
    const float* Wh = (const float*)d_in[3];  // [NH][NH]
    const float* Wy = (const float*)d_in[4];  // [NY][NH]

    float* y  = (float*)d_out;                         // [B][T][NY]
    float* hs = y + (size_t)B_ * T_ * NY_;             // [B][T][NH]

    // Initialize recurrent state buffer 0 from the h input (replayed per launch).
    void* ghp = nullptr;
    cudaGetSymbolAddress(&ghp, g_h);
    cudaMemcpyAsync(ghp, h0, (size_t)B_ * NH_ * sizeof(float),
                    cudaMemcpyDeviceToDevice, 0);

    // Phase 1: pre = x @ Wi^T  -> hs region (scratch)
    {
        dim3 grid(NH_ / 64, (B_ * T_) / 128);
        sgemm_nt<128, 64, 16, 8, 4, 256><<<grid, 256>>>(x, Wi, hs, B_ * T_, NH_, NX_);
    }

    // Phase 2: sequential recurrence (persistent kernel, grid barrier)
    {
        const int smem = (512 * 32 + 512 * 16 + 8 * 512) * (int)sizeof(float); // 114688
        cudaFuncSetAttribute(rnn_seq, cudaFuncAttributeMaxDynamicSharedMemorySize, smem);
        rnn_seq<<<SEQ_NBLK, 256, smem>>>(Wh, hs);
    }

    // Phase 3: y = hs @ Wy^T
    {
        dim3 grid(NY_ / 64, (B_ * T_) / 128);
        sgemm_nt<128, 64, 16, 8, 4, 256><<<grid, 256>>>(hs, Wy, y, B_ * T_, NY_, NH_);
    }
}